// round 6
// baseline (speedup 1.0000x reference)
#include <cuda_runtime.h>
#include <cstdint>

#define FEAT      256
#define PRE_CAP   16384
#define PRE_SHIFT 14
#define JT        16
#define DEF_INSERT 999000
#define NBLK      592
#define NTHR      256
#define NT        (NBLK * NTHR)

typedef unsigned long long u64;

// ---------------- device scratch (no allocations allowed) ----------------
__device__ u64      g_pre[PRE_CAP];        // ((0x7FFFFF - r) << 32) | index
__device__ int      g_npre;                // zero-init; reset in phase D each run
__device__ int      g_rankp[JT][PRE_CAP];  // partial rank counts per j-tile
__device__ uint32_t g_topidx[PRE_CAP];     // ordered sampled indices
__device__ int      g_bar_count;
__device__ volatile unsigned g_bar_gen;

// ---------------- Threefry-2x32, 20 rounds, partitionable layout (JAX-exact) ----------------
__device__ __forceinline__ uint32_t rotl32(uint32_t x, int d) {
    return (x << d) | (x >> (32 - d));
}

__device__ __forceinline__ uint32_t jax_bits32(uint32_t j) {
    const uint32_t k0 = 0u, k1 = 42u;
    const uint32_t ks2 = k0 ^ k1 ^ 0x1BD11BDAu;
    uint32_t x0 = 0u + k0, x1 = j + k1;
#define TF_R(r) { x0 += x1; x1 = rotl32(x1, (r)); x1 ^= x0; }
    TF_R(13) TF_R(15) TF_R(26) TF_R(6)   x0 += k1;  x1 += ks2 + 1u;
    TF_R(17) TF_R(29) TF_R(16) TF_R(24)  x0 += ks2; x1 += k0  + 2u;
    TF_R(13) TF_R(15) TF_R(26) TF_R(6)   x0 += k0;  x1 += k1  + 3u;
    TF_R(17) TF_R(29) TF_R(16) TF_R(24)  x0 += k1;  x1 += ks2 + 4u;
    TF_R(13) TF_R(15) TF_R(26) TF_R(6)   x0 += ks2; x1 += k0  + 5u;
#undef TF_R
    return x0 ^ x1;   // XOR-fold (jax_threefry_partitionable)
}

__device__ __forceinline__ int read_scalar(const int* p, int defv) {
    return p ? p[0] : defv;
}

// ---------------- grid-wide barrier (all NBLK blocks guaranteed resident) ----------------
__device__ __forceinline__ void grid_bar() {
    __syncthreads();
    if (threadIdx.x == 0) {
        unsigned gen = g_bar_gen;
        __threadfence();
        if (atomicAdd(&g_bar_count, 1) == NBLK - 1) {
            atomicExch(&g_bar_count, 0);
            __threadfence();
            g_bar_gen = gen + 1;
        } else {
            while (g_bar_gen == gen) { }
        }
    }
    __syncthreads();
}

// ---------------- the whole pipeline in one persistent kernel ----------------
__global__ void __launch_bounds__(NTHR, 4)
k_all(const float* __restrict__ buf, const float* __restrict__ tr,
      const int* __restrict__ d_ins, const int* __restrict__ d_size,
      float* __restrict__ out, int max_size, int data_len, int nsamp) {
    const int gtid = blockIdx.x * NTHR + threadIdx.x;
    const int lane = threadIdx.x & 31;

    // ---- Phase A: hash all slots, push top-region survivors ----
    int new_size = read_scalar(d_size, max_size) + data_len;
    if (new_size > max_size) new_size = max_size;
    if (new_size < 0) new_size = 0;

    uint32_t precut = 0u;   // keep ~1.25 * nsamp expected survivors
    if (new_size > 0) {
        u64 keep = ((u64)nsamp * 5u / 4u) << 23;
        keep /= (u64)new_size;
        precut = (keep >= 0x800000ull) ? 0u : (uint32_t)(0x800000ull - keep);
    }

    for (int j = gtid; j - lane < max_size; j += NT) {
        uint32_t r = 0u;
        bool push = false;
        if (j < new_size) {
            r = jax_bits32((uint32_t)j) >> 9;   // 23-bit mantissa; monotone w/ uniform
            push = (r >= precut);
        }
        unsigned mask = __ballot_sync(0xFFFFFFFFu, push);
        if (mask) {
            int leader = __ffs(mask) - 1;
            int base = 0;
            if (lane == leader) base = atomicAdd(&g_npre, __popc(mask));
            base = __shfl_sync(0xFFFFFFFFu, base, leader);
            if (push) {
                int pos = base + __popc(mask & ((1u << lane) - 1u));
                if (pos < PRE_CAP)
                    g_pre[pos] = ((u64)(0x7FFFFFu - r) << 32) | (uint32_t)j;
            }
        }
    }

    grid_bar();

    // ---- Phase B: exact-rank partials over (j-tile, candidate) pairs ----
    int npre = g_npre;
    if (npre > PRE_CAP) npre = PRE_CAP;
    int chunk = (npre + JT - 1) / JT;

    for (int p = gtid; p < JT * PRE_CAP; p += NT) {
        int t  = p & (PRE_CAP - 1);     // consecutive lanes -> consecutive t
        int jt = p >> PRE_SHIFT;        // same j-tile across the warp
        if (t >= npre) continue;
        u64 mykey = g_pre[t];
        int j0 = jt * chunk;
        int j1 = j0 + chunk; if (j1 > npre) j1 = npre;
        int cnt = 0, j = j0;
        for (; j + 4 <= j1; j += 4) {   // L1-broadcast loads, 4-way MLP
            u64 a = g_pre[j], b = g_pre[j + 1], c = g_pre[j + 2], d = g_pre[j + 3];
            cnt += (a < mykey) + (b < mykey) + (c < mykey) + (d < mykey);
        }
        for (; j < j1; ++j) cnt += (g_pre[j] < mykey);
        g_rankp[jt][t] = cnt;
    }

    grid_bar();

    // ---- Phase C: finalize ranks -> ordered index list ----
    if (gtid < npre) {
        int rank = 0;
#pragma unroll
        for (int jt = 0; jt < JT; ++jt) rank += g_rankp[jt][gtid];
        if (rank < nsamp) g_topidx[rank] = (uint32_t)g_pre[gtid];
    }

    grid_bar();

    // ---- Phase D: dense gather (ring-buffer insert resolved on the fly) ----
    if (gtid == 0) g_npre = 0;          // deterministic reset for next run/replay

    long p_ins = (long)(read_scalar(d_ins, DEF_INSERT) % max_size);
    int nelem = nsamp * (FEAT / 4);
    for (int e = gtid; e < nelem; e += NT) {
        int row = e >> 6;
        int c   = e & 63;
        uint32_t idx = g_topidx[row];
        long off = (long)idx - p_ins;
        if (off < 0) off += max_size;
        const float4* src = (off < (long)data_len)
            ? (const float4*)(tr + (size_t)off * FEAT)
            : (const float4*)(buf + (size_t)idx * FEAT);
        ((float4*)(out + (size_t)row * FEAT))[c] = src[c];
    }
}

// ---------------- launcher ----------------
extern "C" void kernel_launch(void* const* d_in, const int* in_sizes, int n_in,
                              void* d_out, int out_size) {
    // Classify inputs by element count (robust to ordering):
    int i_buf = -1, i_tr = -1;
    int sc[3] = { -1, -1, -1 };
    int nsc = 0;
    for (int i = 0; i < n_in; ++i) {
        if (in_sizes[i] > 100000000)      i_buf = i;
        else if (in_sizes[i] > 1000000)   i_tr  = i;
        else if (in_sizes[i] >= 1 && in_sizes[i] <= 4 && nsc < 3) sc[nsc++] = i;
    }
    if (i_buf < 0) i_buf = 0;
    if (i_tr  < 0) i_tr  = 1;

    const float* buf   = (const float*)d_in[i_buf];
    const float* tr    = (const float*)d_in[i_tr];
    const int*   d_ins = (sc[0] >= 0) ? (const int*)d_in[sc[0]] : nullptr;
    const int*   d_sz  = (sc[1] >= 0) ? (const int*)d_in[sc[1]] : nullptr;

    int max_size = in_sizes[i_buf] / FEAT;   // 1,000,000
    int data_len = in_sizes[i_tr]  / FEAT;   // 16,384
    int nsamp    = out_size        / FEAT;   // 4,096

    k_all<<<NBLK, NTHR>>>(buf, tr, d_ins, d_sz, (float*)d_out,
                          max_size, data_len, nsamp);
}

// round 7
// speedup vs baseline: 1.1163x; 1.1163x over previous
#include <cuda_runtime.h>
#include <cstdint>

#define FEAT      256
#define PRE_CAP   16384
#define DEF_INSERT 999000

typedef unsigned long long u64;

// ---------------- device scratch (no allocations allowed) ----------------
__device__ u64      g_pre[PRE_CAP];     // ((0x7FFFFF - r) << 32) | index
__device__ int      g_npre;             // zero-init; reset in k_gather each run
__device__ uint32_t g_topidx[PRE_CAP];  // ordered sampled indices

// ---------------- Threefry-2x32, 20 rounds, partitionable layout (JAX-exact) ----------------
__device__ __forceinline__ uint32_t rotl32(uint32_t x, int d) {
    return (x << d) | (x >> (32 - d));
}

__device__ __forceinline__ uint32_t jax_bits32(uint32_t j) {
    const uint32_t k0 = 0u, k1 = 42u;
    const uint32_t ks2 = k0 ^ k1 ^ 0x1BD11BDAu;
    uint32_t x0 = 0u + k0, x1 = j + k1;
#define TF_R(r) { x0 += x1; x1 = rotl32(x1, (r)); x1 ^= x0; }
    TF_R(13) TF_R(15) TF_R(26) TF_R(6)   x0 += k1;  x1 += ks2 + 1u;
    TF_R(17) TF_R(29) TF_R(16) TF_R(24)  x0 += ks2; x1 += k0  + 2u;
    TF_R(13) TF_R(15) TF_R(26) TF_R(6)   x0 += k0;  x1 += k1  + 3u;
    TF_R(17) TF_R(29) TF_R(16) TF_R(24)  x0 += k1;  x1 += ks2 + 4u;
    TF_R(13) TF_R(15) TF_R(26) TF_R(6)   x0 += ks2; x1 += k0  + 5u;
#undef TF_R
    return x0 ^ x1;   // XOR-fold (jax_threefry_partitionable)
}

__device__ __forceinline__ int read_scalar(const int* p, int defv) {
    return p ? p[0] : defv;
}

// ---------------- K1: hash all slots, push top-region survivors ----------------
__global__ void k_hash_push(const int* __restrict__ d_size,
                            int max_size, int data_len, int nsamp) {
    int new_size = read_scalar(d_size, max_size) + data_len;
    if (new_size > max_size) new_size = max_size;
    if (new_size < 0) new_size = 0;

    // keep top `keep` mantissa values so expected survivors ~= 1.25 * nsamp
    uint32_t precut = 0u;
    if (new_size > 0) {
        u64 keep = ((u64)nsamp * 5u / 4u) << 23;
        keep /= (u64)new_size;
        precut = (keep >= 0x800000ull) ? 0u : (uint32_t)(0x800000ull - keep);
    }

    const int lane = threadIdx.x & 31;
    const int stride = gridDim.x * blockDim.x;
    for (int j = blockIdx.x * blockDim.x + threadIdx.x;
         j - lane < max_size; j += stride) {
        uint32_t r = 0u;
        bool push = false;
        if (j < new_size) {
            r = jax_bits32((uint32_t)j) >> 9;   // 23-bit mantissa; monotone w/ uniform
            push = (r >= precut);
        }
        unsigned mask = __ballot_sync(0xFFFFFFFFu, push);
        if (mask) {
            int leader = __ffs(mask) - 1;
            int base = 0;
            if (lane == leader) base = atomicAdd(&g_npre, __popc(mask));
            base = __shfl_sync(0xFFFFFFFFu, base, leader);
            if (push) {
                int pos = base + __popc(mask & ((1u << lane) - 1u));
                if (pos < PRE_CAP)
                    g_pre[pos] = ((u64)(0x7FFFFFu - r) << 32) | (uint32_t)j;
            }
        }
    }
}

// ---------------- K2: warp-per-candidate exact rank -> ordered index list ----------------
__global__ void k_rank(int nsamp) {
    int npre = g_npre;
    if (npre > PRE_CAP) npre = PRE_CAP;

    const int lane   = threadIdx.x & 31;
    const int warp   = (blockIdx.x * blockDim.x + threadIdx.x) >> 5;
    const int nwarps = (gridDim.x * blockDim.x) >> 5;

    for (int t = warp; t < npre; t += nwarps) {
        u64 mykey = g_pre[t];               // same addr across warp -> broadcast
        int cnt = 0;
        // lanes stride the list: coalesced 256B/warp loads, L1-resident after 1st pass
        int j = lane;
        for (; j + 128 <= npre; j += 128) {
            u64 a = g_pre[j];
            u64 b = g_pre[j + 32];
            u64 c = g_pre[j + 64];
            u64 d = g_pre[j + 96];
            cnt += (a < mykey) + (b < mykey) + (c < mykey) + (d < mykey);
        }
        for (; j < npre; j += 32) cnt += (g_pre[j] < mykey);
        int rank = __reduce_add_sync(0xFFFFFFFFu, cnt);
        if (lane == 0 && rank < nsamp)
            g_topidx[rank] = (uint32_t)mykey;
    }
}

// ---------------- K3: dense gather, MLP=2 (ring-buffer insert resolved on the fly) ----------------
__global__ void k_gather(const float* __restrict__ buf, const float* __restrict__ tr,
                         const int* __restrict__ d_ins, float* __restrict__ out,
                         int max_size, int data_len, int nsamp) {
    if (blockIdx.x == 0 && threadIdx.x == 0) g_npre = 0;  // deterministic reset

    const long p_ins = (long)(read_scalar(d_ins, DEF_INSERT) % max_size);
    const int nelem  = nsamp * (FEAT / 4);        // total float4s
    const int halfe  = nelem >> 1;
    int e = blockIdx.x * blockDim.x + threadIdx.x;
    if (e >= halfe) return;

    int row0 = e >> 6,            c0 = e & 63;
    int row1 = (e + halfe) >> 6,  c1 = e & 63;

    uint32_t i0 = g_topidx[row0];                 // two independent chains
    uint32_t i1 = g_topidx[row1];

    long off0 = (long)i0 - p_ins; if (off0 < 0) off0 += max_size;
    long off1 = (long)i1 - p_ins; if (off1 < 0) off1 += max_size;

    const float4* s0 = (off0 < (long)data_len)
        ? (const float4*)(tr + (size_t)off0 * FEAT)
        : (const float4*)(buf + (size_t)i0 * FEAT);
    const float4* s1 = (off1 < (long)data_len)
        ? (const float4*)(tr + (size_t)off1 * FEAT)
        : (const float4*)(buf + (size_t)i1 * FEAT);

    float4 v0 = s0[c0];                           // both loads issued before stores
    float4 v1 = s1[c1];
    ((float4*)(out + (size_t)row0 * FEAT))[c0] = v0;
    ((float4*)(out + (size_t)row1 * FEAT))[c1] = v1;
}

// ---------------- launcher ----------------
extern "C" void kernel_launch(void* const* d_in, const int* in_sizes, int n_in,
                              void* d_out, int out_size) {
    // Classify inputs by element count (robust to ordering):
    int i_buf = -1, i_tr = -1;
    int sc[3] = { -1, -1, -1 };
    int nsc = 0;
    for (int i = 0; i < n_in; ++i) {
        if (in_sizes[i] > 100000000)      i_buf = i;
        else if (in_sizes[i] > 1000000)   i_tr  = i;
        else if (in_sizes[i] >= 1 && in_sizes[i] <= 4 && nsc < 3) sc[nsc++] = i;
    }
    if (i_buf < 0) i_buf = 0;
    if (i_tr  < 0) i_tr  = 1;

    const float* buf   = (const float*)d_in[i_buf];
    const float* tr    = (const float*)d_in[i_tr];
    const int*   d_ins = (sc[0] >= 0) ? (const int*)d_in[sc[0]] : nullptr;
    const int*   d_sz  = (sc[1] >= 0) ? (const int*)d_in[sc[1]] : nullptr;

    int max_size = in_sizes[i_buf] / FEAT;   // 1,000,000
    int data_len = in_sizes[i_tr]  / FEAT;   // 16,384
    int nsamp    = out_size        / FEAT;   // 4,096

    k_hash_push<<<512, 256>>>(d_sz, max_size, data_len, nsamp);
    k_rank<<<640, 256>>>(nsamp);             // 5120 warps: 1 per expected candidate
    int halfe = (nsamp * (FEAT / 4)) / 2;    // 131072 threads, 2 float4 each
    k_gather<<<(halfe + 255) / 256, 256>>>(buf, tr, d_ins, (float*)d_out,
                                           max_size, data_len, nsamp);
}